// round 15
// baseline (speedup 1.0000x reference)
#include <cuda_runtime.h>
#include <cuda_fp16.h>
#include <math.h>

// ---------------- problem constants ----------------
#define BB 2
#define LL 2048
#define DM 512
#define DK 64
#define NH 8
#define RK 32
#define RF 128
#define KM 64
#define NG 8
#define NROWS (BB*LL)          // 4096
#define CR 256                 // NH*RK

#define RFF_SCALE 0.125f                   // sqrt(2/128)
#define INV_SQRT_RF 0.08838834764831845f   // 1/sqrt(128)

// ---------------- scratch ----------------
__device__ float g_qdown[NROWS*DK];
__device__ float g_kdown[NROWS*DK];
__device__ float g_vdown[NROWS*DK];
__device__ float g_A[NH*DK*DK];
__device__ float g_tmp[NH*RK*DM];          // (256, 512) stacked
__device__ float g_vr[(size_t)NROWS*CR];   // v_down @ U  (4096, 256)
__device__ float g_cr[(size_t)NROWS*CR];   // rank-space ctx (4096, 256)
__device__ __half g_phiq[(size_t)NH*NROWS*RF];
__device__ __half g_phik[(size_t)NH*NROWS*RF];
__device__ unsigned long long g_qcodes[(size_t)NH*NROWS];
__device__ unsigned char g_kcodes[NROWS*NG];
__device__ short g_bucket[BB*NG*256*KM];
__device__ int   g_bcnt[BB*NG*256];

// ---------------- K0: A_h = W_UQ^T @ W_UK ----------------
__global__ void k_precompA(const float* __restrict__ u_q, const float* __restrict__ v_q,
                           const float* __restrict__ u_k, const float* __restrict__ v_k){
    int h = blockIdx.x;
    __shared__ float WQ[DK*DK];
    __shared__ float WK[DK*DK];
    const float* uq = u_q + h*DK*RK;
    const float* vq = v_q + h*RK*DK;
    const float* uk = u_k + h*DK*RK;
    const float* vk = v_k + h*RK*DK;
    for (int e = threadIdx.x; e < DK*DK; e += blockDim.x){
        int i = e >> 6, j = e & 63;
        float a = 0.f, b = 0.f;
        #pragma unroll
        for (int r = 0; r < RK; r++){
            a += uq[i*RK+r]*vq[r*DK+j];
            b += uk[i*RK+r]*vk[r*DK+j];
        }
        WQ[e] = a; WK[e] = b;
    }
    __syncthreads();
    for (int e = threadIdx.x; e < DK*DK; e += blockDim.x){
        int i = e >> 6, j = e & 63;
        float a = 0.f;
        #pragma unroll 8
        for (int d = 0; d < DK; d++) a += WQ[d*DK+i]*WK[d*DK+j];
        g_A[h*DK*DK + e] = a;
    }
}

// ---------------- K1: tmp[h] = v_v[h] @ W_out slice (2-way K split) ----------------
__global__ __launch_bounds__(256) void k_tmp(const float* __restrict__ v_v,
                                             const float* __restrict__ W_out){
    int h  = blockIdx.x;
    int t  = threadIdx.x;
    int jl = t & 127;
    int half = t >> 7;
    int j  = blockIdx.y*128 + jl;
    const float* vv = v_v + (size_t)h*RK*DM;
    const float* wo = W_out + (size_t)h*DM*DM;
    __shared__ float red[RK][128];
    float acc[RK];
    #pragma unroll
    for (int r = 0; r < RK; r++) acc[r] = 0.f;
    int d0 = half*256;
    for (int d = d0; d < d0+256; d++){
        float w = wo[(size_t)d*DM + j];
        #pragma unroll
        for (int r = 0; r < RK; r++) acc[r] += vv[r*DM+d]*w;
    }
    if (half == 1){
        #pragma unroll
        for (int r = 0; r < RK; r++) red[r][jl] = acc[r];
    }
    __syncthreads();
    if (half == 0){
        #pragma unroll
        for (int r = 0; r < RK; r++)
            g_tmp[((size_t)h*RK+r)*DM + j] = acc[r] + red[r][jl];
    }
}

// ---------------- K3: fused down projections (128 rows, Ktile16, db, 8x4/thread) ----------------
__global__ __launch_bounds__(256) void k_down(const float* __restrict__ q, const float* __restrict__ k,
                       const float* __restrict__ v, const float* __restrict__ Wq,
                       const float* __restrict__ bq, const float* __restrict__ Wkv,
                       const float* __restrict__ bkv){
    int which = blockIdx.y;
    int row0  = blockIdx.x * 128;
    const float* src  = (which==0) ? q : ((which==1) ? k : v);
    const float* W    = (which==0) ? Wq : Wkv;
    const float* bias = (which==0) ? bq : bkv;

    __shared__ float As[2][16][132];
    __shared__ float Ws[2][16][64];
    int t = threadIdx.x;
    int tm = (t >> 4) * 8;
    int tn = (t & 15) * 4;
    int lr = t >> 1;
    int lc = (t & 1) * 8;
    int lk = t >> 4;
    int ln = (t & 15) * 4;

    float acc[8][4];
    #pragma unroll
    for (int i = 0; i < 8; i++)
        #pragma unroll
        for (int j = 0; j < 4; j++) acc[i][j] = 0.f;

    {
        float4 a0 = *(const float4*)&src[(size_t)(row0+lr)*DM + lc];
        float4 a1 = *(const float4*)&src[(size_t)(row0+lr)*DM + lc + 4];
        float4 vw = *(const float4*)&W[(size_t)lk*DK + ln];
        As[0][lc+0][lr]=a0.x; As[0][lc+1][lr]=a0.y; As[0][lc+2][lr]=a0.z; As[0][lc+3][lr]=a0.w;
        As[0][lc+4][lr]=a1.x; As[0][lc+5][lr]=a1.y; As[0][lc+6][lr]=a1.z; As[0][lc+7][lr]=a1.w;
        *(float4*)&Ws[0][lk][ln] = vw;
    }
    __syncthreads();

    int cur = 0;
    #pragma unroll 1
    for (int kt = 0; kt < 32; kt++){
        float4 a0, a1, vw;
        if (kt < 31){
            int k0 = (kt+1)*16;
            a0 = *(const float4*)&src[(size_t)(row0+lr)*DM + k0 + lc];
            a1 = *(const float4*)&src[(size_t)(row0+lr)*DM + k0 + lc + 4];
            vw = *(const float4*)&W[(size_t)(k0+lk)*DK + ln];
        }
        #pragma unroll
        for (int kk = 0; kk < 16; kk++){
            float a[8];
            #pragma unroll
            for (int i = 0; i < 8; i++) a[i] = As[cur][kk][tm+i];
            float4 b4 = *(float4*)&Ws[cur][kk][tn];
            #pragma unroll
            for (int i = 0; i < 8; i++){
                acc[i][0] += a[i]*b4.x; acc[i][1] += a[i]*b4.y;
                acc[i][2] += a[i]*b4.z; acc[i][3] += a[i]*b4.w;
            }
        }
        if (kt < 31){
            int nxt = cur ^ 1;
            As[nxt][lc+0][lr]=a0.x; As[nxt][lc+1][lr]=a0.y; As[nxt][lc+2][lr]=a0.z; As[nxt][lc+3][lr]=a0.w;
            As[nxt][lc+4][lr]=a1.x; As[nxt][lc+5][lr]=a1.y; As[nxt][lc+6][lr]=a1.z; As[nxt][lc+7][lr]=a1.w;
            *(float4*)&Ws[nxt][lk][ln] = vw;
        }
        __syncthreads();
        cur ^= 1;
    }

    float4 bi = *(const float4*)&bias[tn];
    #pragma unroll
    for (int i = 0; i < 8; i++){
        acc[i][0]+=bi.x; acc[i][1]+=bi.y; acc[i][2]+=bi.z; acc[i][3]+=bi.w;
    }

    float* dst = (which==0) ? g_qdown : ((which==1) ? g_kdown : g_vdown);
    #pragma unroll
    for (int i = 0; i < 8; i++)
        *(float4*)&dst[(size_t)(row0+tm+i)*DK + tn] =
            make_float4(acc[i][0], acc[i][1], acc[i][2], acc[i][3]);

    if (which == 1){
        unsigned pack = 0;
        #pragma unroll
        for (int i = 0; i < 8; i++)
            #pragma unroll
            for (int j = 0; j < 4; j++)
                pack |= ((acc[i][j] > 0.f) ? 1u : 0u) << (i*4 + j);
        unsigned other = __shfl_xor_sync(0xffffffffu, pack, 1);
        if ((t & 1) == 0){
            int g2 = (t & 15) >> 1;
            #pragma unroll
            for (int i = 0; i < 8; i++){
                int code = (int)((pack >> (i*4)) & 15u) | ((int)((other >> (i*4)) & 15u) << 4);
                g_kcodes[(row0+tm+i)*NG + g2] = (unsigned char)code;
            }
        }
    }
}

// ---------------- K3b: vr = v_down @ U ----------------
__global__ __launch_bounds__(256) void k_vr(const float* __restrict__ u_v){
    int row0 = blockIdx.x * 64;
    int c0   = blockIdx.y * 64;
    __shared__ float Vs[64][65];
    __shared__ float Us[64][64];
    int t = threadIdx.x;
    #pragma unroll
    for (int p = 0; p < 4; p++){
        int lin = t + p*256;
        int r = lin >> 4, d = (lin & 15)*4;
        float4 v = *(const float4*)&g_vdown[(size_t)(row0+r)*DK + d];
        Vs[r][d]=v.x; Vs[r][d+1]=v.y; Vs[r][d+2]=v.z; Vs[r][d+3]=v.w;
    }
    #pragma unroll
    for (int p = 0; p < 4; p++){
        int lin = t + p*256;
        int d = lin >> 4, cc = (lin & 15)*4;
        int c = c0 + cc;
        int h = c >> 5, r = c & 31;
        float4 u = *(const float4*)&u_v[(size_t)h*DK*RK + d*RK + r];
        *(float4*)&Us[d][cc] = u;
    }
    __syncthreads();
    int tm = (t >> 4) * 4;
    int tn = (t & 15) * 4;
    float acc[4][4];
    #pragma unroll
    for (int i = 0; i < 4; i++)
        #pragma unroll
        for (int j = 0; j < 4; j++) acc[i][j] = 0.f;
    #pragma unroll 8
    for (int d = 0; d < DK; d++){
        float a[4], b[4];
        #pragma unroll
        for (int i = 0; i < 4; i++) a[i] = Vs[tm+i][d];
        #pragma unroll
        for (int j = 0; j < 4; j++) b[j] = Us[d][tn+j];
        #pragma unroll
        for (int i = 0; i < 4; i++)
            #pragma unroll
            for (int j = 0; j < 4; j++) acc[i][j] += a[i]*b[j];
    }
    #pragma unroll
    for (int i = 0; i < 4; i++)
        *(float4*)&g_vr[(size_t)(row0+tm+i)*CR + c0 + tn] =
            make_float4(acc[i][0], acc[i][1], acc[i][2], acc[i][3]);
}

// ---------------- K4: fused phi (z=0: phi_q + q-codes, z=1: phi_k) ----------------
__global__ __launch_bounds__(128) void k_phi(const float* __restrict__ omega,
                                             const float* __restrict__ rff_bias){
    int row0 = blockIdx.x * 32;
    int h    = blockIdx.y;
    int isQ  = (blockIdx.z == 0);
    __shared__ float xs[32][64];
    __shared__ float Ash[64][64];
    __shared__ float qp[32][65];
    int t = threadIdx.x;

    const float* srcdown = isQ ? g_qdown : g_kdown;
    #pragma unroll
    for (int p = 0; p < 4; p++){
        int lin = t + p*128;
        int r = lin >> 4, c = (lin & 15)*4;
        *(float4*)&xs[r][c] = *(const float4*)&srcdown[(size_t)(row0+r)*DK + c];
    }

    if (isQ){
        const float* Ah = g_A + h*DK*DK;
        #pragma unroll
        for (int p = 0; p < 8; p++){
            int lin = t + p*128;
            int d = lin >> 4, j = (lin & 15)*4;
            *(float4*)&Ash[d][j] = *(const float4*)&Ah[d*DK + j];
        }
        __syncthreads();
        #pragma unroll 2
        for (int i = 0; i < 16; i++){
            int e = t + 128*i;
            int r = e >> 6, j = e & 63;
            float a = 0.f;
            #pragma unroll
            for (int d = 0; d < 64; d++) a += xs[r][d]*Ash[d][j];
            qp[r][j] = a;
        }
        __syncthreads();
        if (t < 32){
            int r = t;
            unsigned long long cc = 0;
            #pragma unroll
            for (int g2 = 0; g2 < 8; g2++){
                int code = 0;
                #pragma unroll
                for (int bb = 0; bb < 8; bb++) code |= ((qp[r][g2*8+bb] > 0.f) ? 1 : 0) << bb;
                cc |= ((unsigned long long)code) << (8*g2);
            }
            g_qcodes[(size_t)h*NROWS + row0 + r] = cc;
        }
    } else {
        __syncthreads();
    }

    float om[64];
    const float* ob = omega + (size_t)h*DK*RF + t;
    #pragma unroll
    for (int d = 0; d < 64; d++) om[d] = ob[(size_t)d*RF];
    float bias = rff_bias[h*RF + t];
    __half* outp = (isQ ? g_phiq : g_phik) + ((size_t)h*NROWS + row0)*RF + t;
    if (isQ){
        #pragma unroll 4
        for (int r = 0; r < 32; r++){
            float s = bias;
            #pragma unroll
            for (int d = 0; d < 64; d++) s += qp[r][d]*om[d];
            outp[(size_t)r*RF] = __float2half(__cosf(s)*RFF_SCALE);
        }
    } else {
        #pragma unroll 4
        for (int r = 0; r < 32; r++){
            float s = bias;
            #pragma unroll
            for (int d = 0; d < 64; d++) s += xs[r][d]*om[d];
            outp[(size_t)r*RF] = __float2half(__cosf(s)*RFF_SCALE);
        }
    }
}

// ---------------- K6: buckets (vectorized byte scan) ----------------
__global__ void k_bucket(){
    int b  = blockIdx.x >> 3;
    int g2 = blockIdx.x & 7;
    __shared__ unsigned int kc4[LL/4];    // packed codes, byte j = code of key j
    int t = threadIdx.x;   // 256 (one per code)
    for (int j = t; j < LL; j += 256)
        ((unsigned char*)kc4)[j] = g_kcodes[(b*LL + j)*NG + g2];
    __syncthreads();
    int cnt = 0;
    short* bp = g_bucket + (((b*NG + g2)*256) + t)*KM;
    unsigned target = (unsigned)t * 0x01010101u;
    #pragma unroll 4
    for (int jw = 0; jw < LL/4; jw++){
        unsigned eq = __vcmpeq4(kc4[jw], target);
        if (eq){
            int j0 = jw*4;
            if (eq & 0x000000FFu){ if (cnt < KM) bp[cnt] = (short)(j0+0); cnt++; }
            if (eq & 0x0000FF00u){ if (cnt < KM) bp[cnt] = (short)(j0+1); cnt++; }
            if (eq & 0x00FF0000u){ if (cnt < KM) bp[cnt] = (short)(j0+2); cnt++; }
            if (eq & 0xFF000000u){ if (cnt < KM) bp[cnt] = (short)(j0+3); cnt++; }
        }
    }
    g_bcnt[(b*NG + g2)*256 + t] = (cnt < KM) ? cnt : KM;
}

// ---------------- K7: warp-per-(row,head) sparse attention -> rank-space ctx ----------------
__global__ __launch_bounds__(256) void k_attn(){
    int row = blockIdx.x;
    int b   = row >> 11;
    int t   = threadIdx.x;
    int lane = t & 31;
    int w    = t >> 5;
    int h    = w;

    __shared__ unsigned int bm[8][64];
    __shared__ int   cand[8][64];
    __shared__ float sw[8][64];

    bm[w][lane] = 0u; bm[w][lane+32] = 0u;
    unsigned long long qc = g_qcodes[(size_t)h*NROWS + row];

    int sub = lane & 7, grp = lane >> 3;
    const uint4* pq4 = (const uint4*)(g_phiq + ((size_t)h*NROWS + row)*RF);
    uint4 qa = pq4[sub];
    uint4 qb = pq4[8 + sub];
    __half2 qh[8];
    {
        const __half2* qha = (const __half2*)&qa;
        const __half2* qhb = (const __half2*)&qb;
        #pragma unroll
        for (int j = 0; j < 4; j++){ qh[j] = qha[j]; qh[4+j] = qhb[j]; }
    }
    __syncwarp();

    #pragma unroll
    for (int g2 = 0; g2 < NG; g2++){
        int c = (int)((qc >> (8*g2)) & 255ull);
        int base = (b*NG + g2)*256 + c;
        int n = g_bcnt[base];
        if (lane < n){
            int j = (int)g_bucket[base*KM + lane];
            atomicOr(&bm[w][j >> 5], 1u << (j & 31));
        }
        if (lane + 32 < n){
            int j = (int)g_bucket[base*KM + lane + 32];
            atomicOr(&bm[w][j >> 5], 1u << (j & 31));
        }
    }
    __syncwarp();

    unsigned w0 = bm[w][2*lane], w1 = bm[w][2*lane+1];
    int c0 = __popc(w0), c1 = __popc(w1);
    int cpair = c0 + c1, incl = cpair;
    #pragma unroll
    for (int off = 1; off < 32; off <<= 1){
        int nn = __shfl_up_sync(0xffffffffu, incl, off);
        if (lane >= off) incl += nn;
    }
    int total = __shfl_sync(0xffffffffu, incl, 31);
    int m = (total < KM) ? total : KM;
    int pre0 = incl - cpair;
    int pre1 = incl - c1;

    {
        int base = pre0;
        if (base < KM){
            unsigned int word = w0;
            while (word){
                int bit = __ffs(word) - 1;
                word &= word - 1;
                cand[w][base] = 64*lane + bit;
                if (++base >= KM) break;
            }
        }
        base = pre1;
        if (base < KM){
            unsigned int word = w1;
            while (word){
                int bit = __ffs(word) - 1;
                word &= word - 1;
                cand[w][base] = 64*lane + 32 + bit;
                if (++base >= KM) break;
            }
        }
    }
    __syncwarp();

    const float4* kb4 = (const float4*)(g_phik + ((size_t)h*NROWS + b*LL)*RF);
    #pragma unroll
    for (int p = 0; p < 16; p++){
        int c = p*4 + grp;
        float s = 0.f;
        if (c < m){
            size_t rbase = (size_t)cand[w][c] * 16;
            float4 ka = kb4[rbase + sub];
            float4 kb = kb4[rbase + 8 + sub];
            const __half2* kha = (const __half2*)&ka;
            const __half2* khb = (const __half2*)&kb;
            __half2 acc2 = __float2half2_rn(0.f);
            #pragma unroll
            for (int j = 0; j < 4; j++) acc2 = __hfma2(qh[j],   kha[j], acc2);
            #pragma unroll
            for (int j = 0; j < 4; j++) acc2 = __hfma2(qh[4+j], khb[j], acc2);
            float2 f = __half22float2(acc2);
            s = f.x + f.y;
        }
        s += __shfl_xor_sync(0xffffffffu, s, 1);
        s += __shfl_xor_sync(0xffffffffu, s, 2);
        s += __shfl_xor_sync(0xffffffffu, s, 4);
        if (sub == 0 && c < m) sw[w][c] = s * INV_SQRT_RF;
    }
    __syncwarp();

    float v0 = (lane < m)    ? sw[w][lane]    : -1e30f;
    float v1 = (lane+32 < m) ? sw[w][lane+32] : -1e30f;
    float mx = fmaxf(v0, v1);
    #pragma unroll
    for (int off = 16; off > 0; off >>= 1)
        mx = fmaxf(mx, __shfl_xor_sync(0xffffffffu, mx, off));
    float e0 = (lane < m)    ? __expf(v0 - mx) : 0.f;
    float e1 = (lane+32 < m) ? __expf(v1 - mx) : 0.f;
    float se = e0 + e1;
    #pragma unroll
    for (int off = 16; off > 0; off >>= 1)
        se += __shfl_xor_sync(0xffffffffu, se, off);
    float inv = (m > 0) ? (1.f / se) : 0.f;
    __syncwarp();
    sw[w][lane]    = e0 * inv;
    sw[w][lane+32] = e1 * inv;
    __syncwarp();

    const float* vrb = g_vr + (size_t)b*LL*CR + h*RK + lane;
    float acc = 0.f;
    #pragma unroll 8
    for (int kk = 0; kk < m; kk++)
        acc += sw[w][kk] * vrb[(size_t)cand[w][kk]*CR];
    g_cr[(size_t)row*CR + h*RK + lane] = acc;
}

// ---------------- K8: OUT = CRmat (4096x256) @ g_tmp (256x512) + b_out ----------------
__global__ __launch_bounds__(256) void k_gemm(const float* __restrict__ bias,
                                              float* __restrict__ out){
    const float* A  = g_cr;
    const float* Bm = g_tmp;
    int bn = blockIdx.x;
    int bm = blockIdx.y;
    __shared__ float As[2][16][132];
    __shared__ float Bs[2][16][64];
    int t = threadIdx.x;
    int tn = (t & 15) * 4;
    int tm = (t >> 4) * 8;
    int lr = t >> 1;
    int lc = (t & 1) * 8;
    int lk = t >> 4;
    int ln = (t & 15) * 4;

    float acc[8][4];
    #pragma unroll
    for (int i = 0; i < 8; i++)
        #pragma unroll
        for (int j = 0; j < 4; j++) acc[i][j] = 0.f;

    {
        float4 a0 = *(const float4*)&A[((size_t)(bm*128 + lr))*CR + lc];
        float4 a1 = *(const float4*)&A[((size_t)(bm*128 + lr))*CR + lc + 4];
        float4 vb = *(const float4*)&Bm[((size_t)lk)*DM + bn*64 + ln];
        As[0][lc+0][lr]=a0.x; As[0][lc+1][lr]=a0.y; As[0][lc+2][lr]=a0.z; As[0][lc+3][lr]=a0.w;
        As[0][lc+4][lr]=a1.x; As[0][lc+5][lr]=a1.y; As[0][lc+6][lr]=a1.z; As[0][lc+7][lr]=a1.w;
        *(float4*)&Bs[0][lk][ln] = vb;
    }
    __syncthreads();

    int cur = 0;
    #pragma unroll 1
    for (int kt = 0; kt < 16; kt++){
        float4 a0, a1, vb;
        if (kt < 15){
            int k0 = (kt+1)*16;
            a0 = *(const float4*)&A[((size_t)(bm*128 + lr))*CR + k0 + lc];
            a1 = *(const float4*)&A[((size_t)(bm*128 + lr))*CR + k0 + lc + 4];
            vb = *(const float4*)&Bm[((size_t)(k0+lk))*DM + bn*64 + ln];
        }
        #pragma unroll
        for (int kk = 0; kk < 16; kk++){
            float a[8], bb[4];
            #pragma unroll
            for (int i = 0; i < 8; i++) a[i] = As[cur][kk][tm+i];
            float4 b4 = *(float4*)&Bs[cur][kk][tn];
            bb[0]=b4.x; bb[1]=b4.y; bb[2]=b4.z; bb[3]=b4.w;
            #pragma unroll
            for (int i = 0; i < 8; i++)
                #pragma unroll
                for (int j = 0; j < 4; j++) acc[i][j] += a[i]*bb[j];
        }
        if (kt < 15){
            int nxt = cur ^ 1;
            As[nxt][lc+0][lr]=a0.x; As[nxt][lc+1][lr]=a0.y; As[nxt][lc+2][lr]=a0.z; As[nxt][lc+3][lr]=a0.w;
            As[nxt][lc+4][lr]=a1.x; As[nxt][lc+5][lr]=a1.y; As[nxt][lc+6][lr]=a1.z; As[nxt][lc+7][lr]=a1.w;
            *(float4*)&Bs[nxt][lk][ln] = vb;
        }
        __syncthreads();
        cur ^= 1;
    }
    float4 bi = *(const float4*)&bias[bn*64 + tn];
    #pragma unroll
    for (int i = 0; i < 8; i++){
        float4 o = make_float4(acc[i][0]+bi.x, acc[i][1]+bi.y, acc[i][2]+bi.z, acc[i][3]+bi.w);
        *(float4*)&out[((size_t)(bm*128 + tm + i))*DM + bn*64 + tn] = o;
    }
}

// ---------------- launch ----------------
extern "C" void kernel_launch(void* const* d_in, const int* in_sizes, int n_in,
                              void* d_out, int out_size){
    const float* query    = (const float*)d_in[0];
    const float* key      = (const float*)d_in[1];
    const float* value    = (const float*)d_in[2];
    const float* Wq       = (const float*)d_in[3];
    const float* bq       = (const float*)d_in[4];
    const float* Wkv      = (const float*)d_in[5];
    const float* bkv      = (const float*)d_in[6];
    const float* u_q      = (const float*)d_in[7];
    const float* v_q      = (const float*)d_in[8];
    const float* u_k      = (const float*)d_in[9];
    const float* v_k      = (const float*)d_in[10];
    const float* u_v      = (const float*)d_in[11];
    const float* v_v      = (const float*)d_in[12];
    const float* omega    = (const float*)d_in[13];
    const float* rff_bias = (const float*)d_in[14];
    const float* W_out    = (const float*)d_in[15];
    const float* b_out    = (const float*)d_in[16];
    float* out = (float*)d_out;

    static cudaStream_t s1, s3;
    static cudaEvent_t eRoot, eA, eM, eDown, eS3, eVr;
    static int inited = 0;
    if (!inited){
        cudaStreamCreateWithFlags(&s1, cudaStreamNonBlocking);
        cudaStreamCreateWithFlags(&s3, cudaStreamNonBlocking);
        cudaEventCreateWithFlags(&eRoot, cudaEventDisableTiming);
        cudaEventCreateWithFlags(&eA,    cudaEventDisableTiming);
        cudaEventCreateWithFlags(&eM,    cudaEventDisableTiming);
        cudaEventCreateWithFlags(&eDown, cudaEventDisableTiming);
        cudaEventCreateWithFlags(&eS3,   cudaEventDisableTiming);
        cudaEventCreateWithFlags(&eVr,   cudaEventDisableTiming);
        inited = 1;
    }

    cudaEventRecord(eRoot, 0);
    cudaStreamWaitEvent(s1, eRoot, 0);
    k_precompA<<<NH, 256, 0, s1>>>(u_q, v_q, u_k, v_k);
    cudaEventRecord(eA, s1);
    k_tmp<<<dim3(NH, 4), 256, 0, s1>>>(v_v, W_out);
    cudaEventRecord(eM, s1);

    // main: down projections
    k_down<<<dim3(NROWS/128, 3), 256>>>(query, key, value, Wq, bq, Wkv, bkv);
    cudaEventRecord(eDown, 0);

    // s3: bucket (vectorized)
    cudaStreamWaitEvent(s3, eDown, 0);
    k_bucket<<<BB*NG, 256, 0, s3>>>();
    cudaEventRecord(eS3, s3);

    // s1: vr after tmp (waits for down)
    cudaStreamWaitEvent(s1, eDown, 0);
    k_vr<<<dim3(NROWS/64, CR/64), 256, 0, s1>>>(u_v);
    cudaEventRecord(eVr, s1);

    // main: fused phi (needs down + A)
    cudaStreamWaitEvent(0, eA, 0);
    k_phi<<<dim3(NROWS/32, NH, 2), 128>>>(omega, rff_bias);

    // join -> attention (needs phi + bucket + vr)
    cudaStreamWaitEvent(0, eS3, 0);
    cudaStreamWaitEvent(0, eVr, 0);
    k_attn<<<NROWS, 256>>>();

    // join tmp -> output GEMM
    cudaStreamWaitEvent(0, eM, 0);
    k_gemm<<<dim3(DM/64, NROWS/128), 256>>>(b_out, out);
}

// round 16
// speedup vs baseline: 1.2027x; 1.2027x over previous
#include <cuda_runtime.h>
#include <cuda_fp16.h>
#include <math.h>

// ---------------- problem constants ----------------
#define BB 2
#define LL 2048
#define DM 512
#define DK 64
#define NH 8
#define RK 32
#define RF 128
#define KM 64
#define NG 8
#define NROWS (BB*LL)          // 4096
#define CR 256                 // NH*RK

#define RFF_SCALE 0.125f                   // sqrt(2/128)
#define INV_SQRT_RF 0.08838834764831845f   // 1/sqrt(128)

// ---------------- scratch ----------------
__device__ float g_qdown[NROWS*DK];
__device__ float g_kdown[NROWS*DK];
__device__ float g_vdown[NROWS*DK];
__device__ float g_A[NH*DK*DK];
__device__ float g_tmp[NH*RK*DM];          // (256, 512) stacked
__device__ float g_vr[(size_t)NROWS*CR];   // v_down @ U  (4096, 256)
__device__ float g_cr[(size_t)NROWS*CR];   // rank-space ctx (4096, 256)
__device__ __half g_phiq[(size_t)NH*NROWS*RF];
__device__ __half g_phik[(size_t)NH*NROWS*RF];
__device__ unsigned long long g_qcodes[(size_t)NH*NROWS];
__device__ unsigned char g_kcodesT[NG*NROWS];   // TRANSPOSED: [g2][row]
__device__ short g_bucket[BB*NG*256*KM];
__device__ int   g_bcnt[BB*NG*256];

// ---------------- K0: A_h = W_UQ^T @ W_UK ----------------
__global__ void k_precompA(const float* __restrict__ u_q, const float* __restrict__ v_q,
                           const float* __restrict__ u_k, const float* __restrict__ v_k){
    int h = blockIdx.x;
    __shared__ float WQ[DK*DK];
    __shared__ float WK[DK*DK];
    const float* uq = u_q + h*DK*RK;
    const float* vq = v_q + h*RK*DK;
    const float* uk = u_k + h*DK*RK;
    const float* vk = v_k + h*RK*DK;
    for (int e = threadIdx.x; e < DK*DK; e += blockDim.x){
        int i = e >> 6, j = e & 63;
        float a = 0.f, b = 0.f;
        #pragma unroll
        for (int r = 0; r < RK; r++){
            a += uq[i*RK+r]*vq[r*DK+j];
            b += uk[i*RK+r]*vk[r*DK+j];
        }
        WQ[e] = a; WK[e] = b;
    }
    __syncthreads();
    for (int e = threadIdx.x; e < DK*DK; e += blockDim.x){
        int i = e >> 6, j = e & 63;
        float a = 0.f;
        #pragma unroll 8
        for (int d = 0; d < DK; d++) a += WQ[d*DK+i]*WK[d*DK+j];
        g_A[h*DK*DK + e] = a;
    }
}

// ---------------- K1: tmp[h] = v_v[h] @ W_out slice (2-way K split) ----------------
__global__ __launch_bounds__(256) void k_tmp(const float* __restrict__ v_v,
                                             const float* __restrict__ W_out){
    int h  = blockIdx.x;
    int t  = threadIdx.x;
    int jl = t & 127;
    int half = t >> 7;
    int j  = blockIdx.y*128 + jl;
    const float* vv = v_v + (size_t)h*RK*DM;
    const float* wo = W_out + (size_t)h*DM*DM;
    __shared__ float red[RK][128];
    float acc[RK];
    #pragma unroll
    for (int r = 0; r < RK; r++) acc[r] = 0.f;
    int d0 = half*256;
    for (int d = d0; d < d0+256; d++){
        float w = wo[(size_t)d*DM + j];
        #pragma unroll
        for (int r = 0; r < RK; r++) acc[r] += vv[r*DM+d]*w;
    }
    if (half == 1){
        #pragma unroll
        for (int r = 0; r < RK; r++) red[r][jl] = acc[r];
    }
    __syncthreads();
    if (half == 0){
        #pragma unroll
        for (int r = 0; r < RK; r++)
            g_tmp[((size_t)h*RK+r)*DM + j] = acc[r] + red[r][jl];
    }
}

// ---------------- K3: fused down projections (128 rows, Ktile16, db, 8x4/thread) ----------------
__global__ __launch_bounds__(256) void k_down(const float* __restrict__ q, const float* __restrict__ k,
                       const float* __restrict__ v, const float* __restrict__ Wq,
                       const float* __restrict__ bq, const float* __restrict__ Wkv,
                       const float* __restrict__ bkv){
    int which = blockIdx.y;
    int row0  = blockIdx.x * 128;
    const float* src  = (which==0) ? q : ((which==1) ? k : v);
    const float* W    = (which==0) ? Wq : Wkv;
    const float* bias = (which==0) ? bq : bkv;

    __shared__ float As[2][16][132];
    __shared__ float Ws[2][16][64];
    int t = threadIdx.x;
    int tm = (t >> 4) * 8;
    int tn = (t & 15) * 4;
    int lr = t >> 1;
    int lc = (t & 1) * 8;
    int lk = t >> 4;
    int ln = (t & 15) * 4;

    float acc[8][4];
    #pragma unroll
    for (int i = 0; i < 8; i++)
        #pragma unroll
        for (int j = 0; j < 4; j++) acc[i][j] = 0.f;

    {
        float4 a0 = *(const float4*)&src[(size_t)(row0+lr)*DM + lc];
        float4 a1 = *(const float4*)&src[(size_t)(row0+lr)*DM + lc + 4];
        float4 vw = *(const float4*)&W[(size_t)lk*DK + ln];
        As[0][lc+0][lr]=a0.x; As[0][lc+1][lr]=a0.y; As[0][lc+2][lr]=a0.z; As[0][lc+3][lr]=a0.w;
        As[0][lc+4][lr]=a1.x; As[0][lc+5][lr]=a1.y; As[0][lc+6][lr]=a1.z; As[0][lc+7][lr]=a1.w;
        *(float4*)&Ws[0][lk][ln] = vw;
    }
    __syncthreads();

    int cur = 0;
    #pragma unroll 1
    for (int kt = 0; kt < 32; kt++){
        float4 a0, a1, vw;
        if (kt < 31){
            int k0 = (kt+1)*16;
            a0 = *(const float4*)&src[(size_t)(row0+lr)*DM + k0 + lc];
            a1 = *(const float4*)&src[(size_t)(row0+lr)*DM + k0 + lc + 4];
            vw = *(const float4*)&W[(size_t)(k0+lk)*DK + ln];
        }
        #pragma unroll
        for (int kk = 0; kk < 16; kk++){
            float a[8];
            #pragma unroll
            for (int i = 0; i < 8; i++) a[i] = As[cur][kk][tm+i];
            float4 b4 = *(float4*)&Ws[cur][kk][tn];
            #pragma unroll
            for (int i = 0; i < 8; i++){
                acc[i][0] += a[i]*b4.x; acc[i][1] += a[i]*b4.y;
                acc[i][2] += a[i]*b4.z; acc[i][3] += a[i]*b4.w;
            }
        }
        if (kt < 31){
            int nxt = cur ^ 1;
            As[nxt][lc+0][lr]=a0.x; As[nxt][lc+1][lr]=a0.y; As[nxt][lc+2][lr]=a0.z; As[nxt][lc+3][lr]=a0.w;
            As[nxt][lc+4][lr]=a1.x; As[nxt][lc+5][lr]=a1.y; As[nxt][lc+6][lr]=a1.z; As[nxt][lc+7][lr]=a1.w;
            *(float4*)&Ws[nxt][lk][ln] = vw;
        }
        __syncthreads();
        cur ^= 1;
    }

    float4 bi = *(const float4*)&bias[tn];
    #pragma unroll
    for (int i = 0; i < 8; i++){
        acc[i][0]+=bi.x; acc[i][1]+=bi.y; acc[i][2]+=bi.z; acc[i][3]+=bi.w;
    }

    float* dst = (which==0) ? g_qdown : ((which==1) ? g_kdown : g_vdown);
    #pragma unroll
    for (int i = 0; i < 8; i++)
        *(float4*)&dst[(size_t)(row0+tm+i)*DK + tn] =
            make_float4(acc[i][0], acc[i][1], acc[i][2], acc[i][3]);

    if (which == 1){
        unsigned pack = 0;
        #pragma unroll
        for (int i = 0; i < 8; i++)
            #pragma unroll
            for (int j = 0; j < 4; j++)
                pack |= ((acc[i][j] > 0.f) ? 1u : 0u) << (i*4 + j);
        unsigned other = __shfl_xor_sync(0xffffffffu, pack, 1);
        if ((t & 1) == 0){
            int g2 = (t & 15) >> 1;
            #pragma unroll
            for (int i = 0; i < 8; i++){
                int code = (int)((pack >> (i*4)) & 15u) | ((int)((other >> (i*4)) & 15u) << 4);
                g_kcodesT[g2*NROWS + row0 + tm + i] = (unsigned char)code;
            }
        }
    }
}

// ---------------- K3b: vr = v_down @ U ----------------
__global__ __launch_bounds__(256) void k_vr(const float* __restrict__ u_v){
    int row0 = blockIdx.x * 64;
    int c0   = blockIdx.y * 64;
    __shared__ float Vs[64][65];
    __shared__ float Us[64][64];
    int t = threadIdx.x;
    #pragma unroll
    for (int p = 0; p < 4; p++){
        int lin = t + p*256;
        int r = lin >> 4, d = (lin & 15)*4;
        float4 v = *(const float4*)&g_vdown[(size_t)(row0+r)*DK + d];
        Vs[r][d]=v.x; Vs[r][d+1]=v.y; Vs[r][d+2]=v.z; Vs[r][d+3]=v.w;
    }
    #pragma unroll
    for (int p = 0; p < 4; p++){
        int lin = t + p*256;
        int d = lin >> 4, cc = (lin & 15)*4;
        int c = c0 + cc;
        int h = c >> 5, r = c & 31;
        float4 u = *(const float4*)&u_v[(size_t)h*DK*RK + d*RK + r];
        *(float4*)&Us[d][cc] = u;
    }
    __syncthreads();
    int tm = (t >> 4) * 4;
    int tn = (t & 15) * 4;
    float acc[4][4];
    #pragma unroll
    for (int i = 0; i < 4; i++)
        #pragma unroll
        for (int j = 0; j < 4; j++) acc[i][j] = 0.f;
    #pragma unroll 8
    for (int d = 0; d < DK; d++){
        float a[4], b[4];
        #pragma unroll
        for (int i = 0; i < 4; i++) a[i] = Vs[tm+i][d];
        #pragma unroll
        for (int j = 0; j < 4; j++) b[j] = Us[d][tn+j];
        #pragma unroll
        for (int i = 0; i < 4; i++)
            #pragma unroll
            for (int j = 0; j < 4; j++) acc[i][j] += a[i]*b[j];
    }
    #pragma unroll
    for (int i = 0; i < 4; i++)
        *(float4*)&g_vr[(size_t)(row0+tm+i)*CR + c0 + tn] =
            make_float4(acc[i][0], acc[i][1], acc[i][2], acc[i][3]);
}

// ---------------- K4: fused phi (z=0: phi_q + q-codes, z=1: phi_k) ----------------
__global__ __launch_bounds__(128) void k_phi(const float* __restrict__ omega,
                                             const float* __restrict__ rff_bias){
    int row0 = blockIdx.x * 32;
    int h    = blockIdx.y;
    int isQ  = (blockIdx.z == 0);
    __shared__ float xs[32][64];
    __shared__ float Ash[64][64];
    __shared__ float qp[32][65];
    int t = threadIdx.x;

    const float* srcdown = isQ ? g_qdown : g_kdown;
    #pragma unroll
    for (int p = 0; p < 4; p++){
        int lin = t + p*128;
        int r = lin >> 4, c = (lin & 15)*4;
        *(float4*)&xs[r][c] = *(const float4*)&srcdown[(size_t)(row0+r)*DK + c];
    }

    if (isQ){
        const float* Ah = g_A + h*DK*DK;
        #pragma unroll
        for (int p = 0; p < 8; p++){
            int lin = t + p*128;
            int d = lin >> 4, j = (lin & 15)*4;
            *(float4*)&Ash[d][j] = *(const float4*)&Ah[d*DK + j];
        }
        __syncthreads();
        #pragma unroll 2
        for (int i = 0; i < 16; i++){
            int e = t + 128*i;
            int r = e >> 6, j = e & 63;
            float a = 0.f;
            #pragma unroll
            for (int d = 0; d < 64; d++) a += xs[r][d]*Ash[d][j];
            qp[r][j] = a;
        }
        __syncthreads();
        if (t < 32){
            int r = t;
            unsigned long long cc = 0;
            #pragma unroll
            for (int g2 = 0; g2 < 8; g2++){
                int code = 0;
                #pragma unroll
                for (int bb = 0; bb < 8; bb++) code |= ((qp[r][g2*8+bb] > 0.f) ? 1 : 0) << bb;
                cc |= ((unsigned long long)code) << (8*g2);
            }
            g_qcodes[(size_t)h*NROWS + row0 + r] = cc;
        }
    } else {
        __syncthreads();
    }

    float om[64];
    const float* ob = omega + (size_t)h*DK*RF + t;
    #pragma unroll
    for (int d = 0; d < 64; d++) om[d] = ob[(size_t)d*RF];
    float bias = rff_bias[h*RF + t];
    __half* outp = (isQ ? g_phiq : g_phik) + ((size_t)h*NROWS + row0)*RF + t;
    if (isQ){
        #pragma unroll 4
        for (int r = 0; r < 32; r++){
            float s = bias;
            #pragma unroll
            for (int d = 0; d < 64; d++) s += qp[r][d]*om[d];
            outp[(size_t)r*RF] = __float2half(__cosf(s)*RFF_SCALE);
        }
    } else {
        #pragma unroll 4
        for (int r = 0; r < 32; r++){
            float s = bias;
            #pragma unroll
            for (int d = 0; d < 64; d++) s += xs[r][d]*om[d];
            outp[(size_t)r*RF] = __float2half(__cosf(s)*RFF_SCALE);
        }
    }
}

// ---------------- K6: buckets (warp-per-(b,g,code), ballot scan) ----------------
__global__ __launch_bounds__(256) void k_bucket(){
    int t = threadIdx.x;
    int lane = t & 31;
    int gw = blockIdx.x * 8 + (t >> 5);    // 0..4095
    int code = gw & 255;
    int bg = gw >> 8;                      // 0..15
    int b = bg >> 3, g2 = bg & 7;
    const unsigned char* kc = g_kcodesT + g2*NROWS + b*LL;
    short* bp = g_bucket + (((b*NG + g2)*256) + code)*KM;
    unsigned char me = (unsigned char)code;
    int cnt = 0;
    for (int j0 = 0; j0 < LL; j0 += 32){
        unsigned char c = kc[j0 + lane];
        unsigned mask = __ballot_sync(0xffffffffu, c == me);
        if (mask){
            if (c == me){
                int pos = cnt + __popc(mask & ((1u << lane) - 1u));
                if (pos < KM) bp[pos] = (short)(j0 + lane);
            }
            cnt += __popc(mask);
            if (cnt >= KM) break;          // warp-uniform (cnt from ballot)
        }
    }
    if (lane == 0)
        g_bcnt[(b*NG + g2)*256 + code] = (cnt < KM) ? cnt : KM;
}

// ---------------- K7: warp-per-(row,head) sparse attention -> rank-space ctx ----------------
__global__ __launch_bounds__(256) void k_attn(){
    int row = blockIdx.x;
    int b   = row >> 11;
    int t   = threadIdx.x;
    int lane = t & 31;
    int w    = t >> 5;
    int h    = w;

    __shared__ unsigned int bm[8][64];
    __shared__ int   cand[8][64];
    __shared__ float sw[8][64];

    bm[w][lane] = 0u; bm[w][lane+32] = 0u;
    unsigned long long qc = g_qcodes[(size_t)h*NROWS + row];

    int sub = lane & 7, grp = lane >> 3;
    const uint4* pq4 = (const uint4*)(g_phiq + ((size_t)h*NROWS + row)*RF);
    uint4 qa = pq4[sub];
    uint4 qb = pq4[8 + sub];
    __half2 qh[8];
    {
        const __half2* qha = (const __half2*)&qa;
        const __half2* qhb = (const __half2*)&qb;
        #pragma unroll
        for (int j = 0; j < 4; j++){ qh[j] = qha[j]; qh[4+j] = qhb[j]; }
    }
    __syncwarp();

    #pragma unroll
    for (int g2 = 0; g2 < NG; g2++){
        int c = (int)((qc >> (8*g2)) & 255ull);
        int base = (b*NG + g2)*256 + c;
        int n = g_bcnt[base];
        if (lane < n){
            int j = (int)g_bucket[base*KM + lane];
            atomicOr(&bm[w][j >> 5], 1u << (j & 31));
        }
        if (lane + 32 < n){
            int j = (int)g_bucket[base*KM + lane + 32];
            atomicOr(&bm[w][j >> 5], 1u << (j & 31));
        }
    }
    __syncwarp();

    unsigned w0 = bm[w][2*lane], w1 = bm[w][2*lane+1];
    int c0 = __popc(w0), c1 = __popc(w1);
    int cpair = c0 + c1, incl = cpair;
    #pragma unroll
    for (int off = 1; off < 32; off <<= 1){
        int nn = __shfl_up_sync(0xffffffffu, incl, off);
        if (lane >= off) incl += nn;
    }
    int total = __shfl_sync(0xffffffffu, incl, 31);
    int m = (total < KM) ? total : KM;
    int pre0 = incl - cpair;
    int pre1 = incl - c1;

    {
        int base = pre0;
        if (base < KM){
            unsigned int word = w0;
            while (word){
                int bit = __ffs(word) - 1;
                word &= word - 1;
                cand[w][base] = 64*lane + bit;
                if (++base >= KM) break;
            }
        }
        base = pre1;
        if (base < KM){
            unsigned int word = w1;
            while (word){
                int bit = __ffs(word) - 1;
                word &= word - 1;
                cand[w][base] = 64*lane + 32 + bit;
                if (++base >= KM) break;
            }
        }
    }
    __syncwarp();

    const float4* kb4 = (const float4*)(g_phik + ((size_t)h*NROWS + b*LL)*RF);
    #pragma unroll
    for (int p = 0; p < 16; p++){
        int c = p*4 + grp;
        float s = 0.f;
        if (c < m){
            size_t rbase = (size_t)cand[w][c] * 16;
            float4 ka = kb4[rbase + sub];
            float4 kb = kb4[rbase + 8 + sub];
            const __half2* kha = (const __half2*)&ka;
            const __half2* khb = (const __half2*)&kb;
            __half2 acc2 = __float2half2_rn(0.f);
            #pragma unroll
            for (int j = 0; j < 4; j++) acc2 = __hfma2(qh[j],   kha[j], acc2);
            #pragma unroll
            for (int j = 0; j < 4; j++) acc2 = __hfma2(qh[4+j], khb[j], acc2);
            float2 f = __half22float2(acc2);
            s = f.x + f.y;
        }
        s += __shfl_xor_sync(0xffffffffu, s, 1);
        s += __shfl_xor_sync(0xffffffffu, s, 2);
        s += __shfl_xor_sync(0xffffffffu, s, 4);
        if (sub == 0 && c < m) sw[w][c] = s * INV_SQRT_RF;
    }
    __syncwarp();

    float v0 = (lane < m)    ? sw[w][lane]    : -1e30f;
    float v1 = (lane+32 < m) ? sw[w][lane+32] : -1e30f;
    float mx = fmaxf(v0, v1);
    #pragma unroll
    for (int off = 16; off > 0; off >>= 1)
        mx = fmaxf(mx, __shfl_xor_sync(0xffffffffu, mx, off));
    float e0 = (lane < m)    ? __expf(v0 - mx) : 0.f;
    float e1 = (lane+32 < m) ? __expf(v1 - mx) : 0.f;
    float se = e0 + e1;
    #pragma unroll
    for (int off = 16; off > 0; off >>= 1)
        se += __shfl_xor_sync(0xffffffffu, se, off);
    float inv = (m > 0) ? (1.f / se) : 0.f;
    __syncwarp();
    sw[w][lane]    = e0 * inv;
    sw[w][lane+32] = e1 * inv;
    __syncwarp();

    const float* vrb = g_vr + (size_t)b*LL*CR + h*RK + lane;
    float acc = 0.f;
    #pragma unroll 8
    for (int kk = 0; kk < m; kk++)
        acc += sw[w][kk] * vrb[(size_t)cand[w][kk]*CR];
    g_cr[(size_t)row*CR + h*RK + lane] = acc;
}

// ---------------- K8: OUT = CRmat (4096x256) @ g_tmp (256x512) + b_out ----------------
__global__ __launch_bounds__(256) void k_gemm(const float* __restrict__ bias,
                                              float* __restrict__ out){
    const float* A  = g_cr;
    const float* Bm = g_tmp;
    int bn = blockIdx.x;
    int bm = blockIdx.y;
    __shared__ float As[2][16][132];
    __shared__ float Bs[2][16][64];
    int t = threadIdx.x;
    int tn = (t & 15) * 4;
    int tm = (t >> 4) * 8;
    int lr = t >> 1;
    int lc = (t & 1) * 8;
    int lk = t >> 4;
    int ln = (t & 15) * 4;

    float acc[8][4];
    #pragma unroll
    for (int i = 0; i < 8; i++)
        #pragma unroll
        for (int j = 0; j < 4; j++) acc[i][j] = 0.f;

    {
        float4 a0 = *(const float4*)&A[((size_t)(bm*128 + lr))*CR + lc];
        float4 a1 = *(const float4*)&A[((size_t)(bm*128 + lr))*CR + lc + 4];
        float4 vb = *(const float4*)&Bm[((size_t)lk)*DM + bn*64 + ln];
        As[0][lc+0][lr]=a0.x; As[0][lc+1][lr]=a0.y; As[0][lc+2][lr]=a0.z; As[0][lc+3][lr]=a0.w;
        As[0][lc+4][lr]=a1.x; As[0][lc+5][lr]=a1.y; As[0][lc+6][lr]=a1.z; As[0][lc+7][lr]=a1.w;
        *(float4*)&Bs[0][lk][ln] = vb;
    }
    __syncthreads();

    int cur = 0;
    #pragma unroll 1
    for (int kt = 0; kt < 16; kt++){
        float4 a0, a1, vb;
        if (kt < 15){
            int k0 = (kt+1)*16;
            a0 = *(const float4*)&A[((size_t)(bm*128 + lr))*CR + k0 + lc];
            a1 = *(const float4*)&A[((size_t)(bm*128 + lr))*CR + k0 + lc + 4];
            vb = *(const float4*)&Bm[((size_t)(k0+lk))*DM + bn*64 + ln];
        }
        #pragma unroll
        for (int kk = 0; kk < 16; kk++){
            float a[8], bb[4];
            #pragma unroll
            for (int i = 0; i < 8; i++) a[i] = As[cur][kk][tm+i];
            float4 b4 = *(float4*)&Bs[cur][kk][tn];
            bb[0]=b4.x; bb[1]=b4.y; bb[2]=b4.z; bb[3]=b4.w;
            #pragma unroll
            for (int i = 0; i < 8; i++)
                #pragma unroll
                for (int j = 0; j < 4; j++) acc[i][j] += a[i]*bb[j];
        }
        if (kt < 15){
            int nxt = cur ^ 1;
            As[nxt][lc+0][lr]=a0.x; As[nxt][lc+1][lr]=a0.y; As[nxt][lc+2][lr]=a0.z; As[nxt][lc+3][lr]=a0.w;
            As[nxt][lc+4][lr]=a1.x; As[nxt][lc+5][lr]=a1.y; As[nxt][lc+6][lr]=a1.z; As[nxt][lc+7][lr]=a1.w;
            *(float4*)&Bs[nxt][lk][ln] = vb;
        }
        __syncthreads();
        cur ^= 1;
    }
    float4 bi = *(const float4*)&bias[bn*64 + tn];
    #pragma unroll
    for (int i = 0; i < 8; i++){
        float4 o = make_float4(acc[i][0]+bi.x, acc[i][1]+bi.y, acc[i][2]+bi.z, acc[i][3]+bi.w);
        *(float4*)&out[((size_t)(bm*128 + tm + i))*DM + bn*64 + tn] = o;
    }
}

// ---------------- launch (R14 graph) ----------------
extern "C" void kernel_launch(void* const* d_in, const int* in_sizes, int n_in,
                              void* d_out, int out_size){
    const float* query    = (const float*)d_in[0];
    const float* key      = (const float*)d_in[1];
    const float* value    = (const float*)d_in[2];
    const float* Wq       = (const float*)d_in[3];
    const float* bq       = (const float*)d_in[4];
    const float* Wkv      = (const float*)d_in[5];
    const float* bkv      = (const float*)d_in[6];
    const float* u_q      = (const float*)d_in[7];
    const float* v_q      = (const float*)d_in[8];
    const float* u_k      = (const float*)d_in[9];
    const float* v_k      = (const float*)d_in[10];
    const float* u_v      = (const float*)d_in[11];
    const float* v_v      = (const float*)d_in[12];
    const float* omega    = (const float*)d_in[13];
    const float* rff_bias = (const float*)d_in[14];
    const float* W_out    = (const float*)d_in[15];
    const float* b_out    = (const float*)d_in[16];
    float* out = (float*)d_out;

    static cudaStream_t s1, s3;
    static cudaEvent_t eRoot, eA, eM, eDown, eS3;
    static int inited = 0;
    if (!inited){
        cudaStreamCreateWithFlags(&s1, cudaStreamNonBlocking);
        cudaStreamCreateWithFlags(&s3, cudaStreamNonBlocking);
        cudaEventCreateWithFlags(&eRoot, cudaEventDisableTiming);
        cudaEventCreateWithFlags(&eA,    cudaEventDisableTiming);
        cudaEventCreateWithFlags(&eM,    cudaEventDisableTiming);
        cudaEventCreateWithFlags(&eDown, cudaEventDisableTiming);
        cudaEventCreateWithFlags(&eS3,   cudaEventDisableTiming);
        inited = 1;
    }

    cudaEventRecord(eRoot, 0);
    cudaStreamWaitEvent(s1, eRoot, 0);
    k_precompA<<<NH, 256, 0, s1>>>(u_q, v_q, u_k, v_k);
    cudaEventRecord(eA, s1);
    k_tmp<<<dim3(NH, 4), 256, 0, s1>>>(v_v, W_out);
    cudaEventRecord(eM, s1);

    // main: down projections
    k_down<<<dim3(NROWS/128, 3), 256>>>(query, key, value, Wq, bq, Wkv, bkv);
    cudaEventRecord(eDown, 0);

    // s3: bucket + vr (both depend only on down outputs)
    cudaStreamWaitEvent(s3, eDown, 0);
    k_bucket<<<BB*NG*256/8, 256, 0, s3>>>();
    k_vr<<<dim3(NROWS/64, CR/64), 256, 0, s3>>>(u_v);
    cudaEventRecord(eS3, s3);

    // main: fused phi (needs down + A)
    cudaStreamWaitEvent(0, eA, 0);
    k_phi<<<dim3(NROWS/32, NH, 2), 128>>>(omega, rff_bias);

    // join -> attention (needs phi + bucket + vr)
    cudaStreamWaitEvent(0, eS3, 0);
    k_attn<<<NROWS, 256>>>();

    // join tmp -> output GEMM
    cudaStreamWaitEvent(0, eM, 0);
    k_gemm<<<dim3(DM/64, NROWS/128), 256>>>(b_out, out);
}